// round 5
// baseline (speedup 1.0000x reference)
#include <cuda_runtime.h>
#include <math.h>

// Problem constants (from reference)
#define NPROJS 128
#define L_DIM  1024
#define S_DIM  256
#define SPACING 4.7952f
#define MU0     0.013f

#define NBLOCKS 128            // one wave; 16 KB of input per block
#define ROWS_PER_BLOCK 8       // one warp per row, 256 threads/block

// Packed accumulator: bits [0:56) fixed-point sum (scale 2^40),
//                     bits [56:64) arrival count.
__device__ unsigned long long g_acc = 0ULL;

#define FIX_SCALE   1099511627776.0f      /* 2^40 */
#define FIX_INV     (1.0 / 1099511627776.0)
#define COUNT_ONE   (1ULL << 56)
#define SUM_MASK    ((1ULL << 56) - 1ULL)

__global__ void __launch_bounds__(256) edcc_fused_kernel(
    const float* __restrict__ projs, float sigma, float* __restrict__ out)
{
    const int lane = threadIdx.x & 31;
    const int warp = threadIdx.x >> 5;      // 0..7 -> row within block
    const int l = blockIdx.x * ROWS_PER_BLOCK + warp;

    // Two used projection slices (i=127, j=29); one warp handles row l.
    const float4* __restrict__ pi = (const float4*)(projs
        + (size_t)127 * L_DIM * S_DIM + (size_t)l * S_DIM);
    const float4* __restrict__ pj = (const float4*)(projs
        + (size_t)29  * L_DIM * S_DIM + (size_t)l * S_DIM);

    // Front-batch all 4 independent 16B loads (max MLP before any use)
    const float4 a0 = pi[lane];
    const float4 a1 = pi[lane + 32];
    const float4 b0 = pj[lane];
    const float4 b1 = pj[lane + 32];

    // Init block accumulator; barrier cost hides under DRAM latency.
    __shared__ unsigned long long s_acc;
    if (threadIdx.x == 0) s_acc = 0ULL;
    __syncthreads();

    // Weight: w(e) = exp(sigma * s(e) * SPACING), s(e) = s_start + e*SPACING
    // (MUFU work also overlaps the in-flight loads)
    const float s_start = (-(float)S_DIM * SPACING + SPACING) * 0.5f;
    const float c1 = sigma * SPACING;
    const float base = c1 * s_start;
    const float step = c1 * SPACING;

    const int e0 = lane * 4;
    const float w0 = __expf(base + (float)(e0 + 0) * step);
    const float w1 = __expf(base + (float)(e0 + 1) * step);
    const float w2 = __expf(base + (float)(e0 + 2) * step);
    const float w3 = __expf(base + (float)(e0 + 3) * step);
    const int e1 = (lane + 32) * 4;
    const float u0 = __expf(base + (float)(e1 + 0) * step);
    const float u1 = __expf(base + (float)(e1 + 1) * step);
    const float u2 = __expf(base + (float)(e1 + 2) * step);
    const float u3 = __expf(base + (float)(e1 + 3) * step);

    float vi = a0.x * w0 + a0.y * w1 + a0.z * w2 + a0.w * w3
             + a1.x * u0 + a1.y * u1 + a1.z * u2 + a1.w * u3;
    float vj = b0.x * w0 + b0.y * w1 + b0.z * w2 + b0.w * w3
             + b1.x * u0 + b1.y * u1 + b1.z * u2 + b1.w * u3;

    // Warp reduction -> P_i, P_j for this row
    #pragma unroll
    for (int off = 16; off > 0; off >>= 1) {
        vi += __shfl_down_sync(0xFFFFFFFFu, vi, off);
        vj += __shfl_down_sync(0xFFFFFFFFu, vj, off);
    }

    if (lane == 0) {
        const float den = vi + vj;
        const float term = (den != 0.0f)
                         ? (2.0f / (float)NPROJS) * fabsf(vi - vj) / den
                         : 0.0f;

        // Block-level packed atomic (integer adds -> deterministic).
        const unsigned long long wcontrib =
            (unsigned long long)(term * FIX_SCALE) | COUNT_ONE;
        const unsigned long long wold = atomicAdd(&s_acc, wcontrib);

        if ((wold >> 56) == (unsigned long long)(ROWS_PER_BLOCK - 1)) {
            // Last warp of this block: forward block total to global atomic.
            const unsigned long long bsum = (wold + wcontrib) & SUM_MASK;
            const unsigned long long gcontrib = bsum | COUNT_ONE;
            const unsigned long long gold = atomicAdd(&g_acc, gcontrib);

            if ((gold >> 56) == (unsigned long long)(NBLOCKS - 1)) {
                const unsigned long long total = (gold + gcontrib) & SUM_MASK;
                out[0] = (float)((double)total * FIX_INV);  // mean over B=1
                g_acc = 0ULL;   // re-arm for next graph replay
            }
        }
    }
}

extern "C" void kernel_launch(void* const* d_in, const int* in_sizes, int n_in,
                              void* d_out, int out_size)
{
    const float* projs = (const float*)d_in[0];
    float* out = (float*)d_out;

    // sigma = MU0 * tan((theta[127] - theta[29]) / 2), theta_k = 2*pi*k/128
    const double two_pi = 6.283185307179586;
    const double th_i = two_pi * 127.0 / 128.0;
    const double th_j = two_pi * 29.0 / 128.0;
    const float sigma = (float)((double)MU0 * tan((th_i - th_j) * 0.5));

    edcc_fused_kernel<<<NBLOCKS, 256>>>(projs, sigma, out);
}

// round 6
// speedup vs baseline: 1.0238x; 1.0238x over previous
#include <cuda_runtime.h>
#include <math.h>

// Problem constants (from reference)
#define NPROJS 128
#define L_DIM  1024
#define S_DIM  256
#define SPACING 4.7952f
#define MU0     0.013f

#define NBLOCKS 128            // one wave; 16 KB of input per block
#define ROWS_PER_BLOCK 8       // one warp per row, 256 threads/block
#define NMID 16                // intermediate accumulators (8 blocks each)
#define MID_STRIDE 32          // 32 * 8B = 256B spacing -> distinct LTS slices

// Packed accumulators: bits [0:56) fixed-point sum (scale 2^40),
//                      bits [56:64) arrival count. All zero at load; each
// level's last arrival resets its own slot for the next graph replay.
__device__ unsigned long long g_mid[NMID * MID_STRIDE];
__device__ unsigned long long g_acc = 0ULL;

#define FIX_SCALE   1099511627776.0f      /* 2^40 */
#define FIX_INV     (1.0 / 1099511627776.0)
#define COUNT_ONE   (1ULL << 56)
#define SUM_MASK    ((1ULL << 56) - 1ULL)

__global__ void __launch_bounds__(256) edcc_fused_kernel(
    const float* __restrict__ projs, float sigma, float* __restrict__ out)
{
    const int lane = threadIdx.x & 31;
    const int warp = threadIdx.x >> 5;      // 0..7 -> row within block
    const int l = blockIdx.x * ROWS_PER_BLOCK + warp;

    // Two used projection slices (i=127, j=29); one warp handles row l.
    const float4* __restrict__ pi = (const float4*)(projs
        + (size_t)127 * L_DIM * S_DIM + (size_t)l * S_DIM);
    const float4* __restrict__ pj = (const float4*)(projs
        + (size_t)29  * L_DIM * S_DIM + (size_t)l * S_DIM);

    // Front-batch all 4 independent 16B loads (max MLP before any use)
    const float4 a0 = pi[lane];
    const float4 a1 = pi[lane + 32];
    const float4 b0 = pj[lane];
    const float4 b1 = pj[lane + 32];

    // Weight: w(e) = exp(sigma * s(e) * SPACING), s(e) = s_start + e*SPACING
    // (MUFU work overlaps the in-flight loads)
    const float s_start = (-(float)S_DIM * SPACING + SPACING) * 0.5f;
    const float c1 = sigma * SPACING;
    const float base = c1 * s_start;
    const float step = c1 * SPACING;

    const int e0 = lane * 4;
    const float w0 = __expf(base + (float)(e0 + 0) * step);
    const float w1 = __expf(base + (float)(e0 + 1) * step);
    const float w2 = __expf(base + (float)(e0 + 2) * step);
    const float w3 = __expf(base + (float)(e0 + 3) * step);
    const int e1 = (lane + 32) * 4;
    const float u0 = __expf(base + (float)(e1 + 0) * step);
    const float u1 = __expf(base + (float)(e1 + 1) * step);
    const float u2 = __expf(base + (float)(e1 + 2) * step);
    const float u3 = __expf(base + (float)(e1 + 3) * step);

    float vi = a0.x * w0 + a0.y * w1 + a0.z * w2 + a0.w * w3
             + a1.x * u0 + a1.y * u1 + a1.z * u2 + a1.w * u3;
    float vj = b0.x * w0 + b0.y * w1 + b0.z * w2 + b0.w * w3
             + b1.x * u0 + b1.y * u1 + b1.z * u2 + b1.w * u3;

    // Warp reduction -> P_i, P_j for this row
    #pragma unroll
    for (int off = 16; off > 0; off >>= 1) {
        vi += __shfl_down_sync(0xFFFFFFFFu, vi, off);
        vj += __shfl_down_sync(0xFFFFFFFFu, vj, off);
    }

    __shared__ float sh_terms[ROWS_PER_BLOCK];
    if (lane == 0) {
        const float den = vi + vj;
        sh_terms[warp] = (den != 0.0f)
                       ? (2.0f / (float)NPROJS) * fabsf(vi - vj) / den
                       : 0.0f;
    }
    __syncthreads();

    // Warp 0: 8-lane parallel read of the terms + 3-shuffle reduce,
    // then two-level deterministic atomic tree.
    if (warp == 0) {
        float bsum = (lane < ROWS_PER_BLOCK) ? sh_terms[lane] : 0.0f;
        bsum += __shfl_down_sync(0xFFFFFFFFu, bsum, 4);
        bsum += __shfl_down_sync(0xFFFFFFFFu, bsum, 2);
        bsum += __shfl_down_sync(0xFFFFFFFFu, bsum, 1);

        if (lane == 0) {
            // Level 1: 8 blocks -> one of 16 mid accumulators.
            unsigned long long* mid = &g_mid[(blockIdx.x >> 3) * MID_STRIDE];
            const unsigned long long contrib =
                (unsigned long long)(bsum * FIX_SCALE) | COUNT_ONE;
            const unsigned long long mold = atomicAdd(mid, contrib);

            if ((mold >> 56) == 7ULL) {                 // 8th arrival at mid
                const unsigned long long msum = (mold + contrib) & SUM_MASK;
                *mid = 0ULL;    // re-arm own slot (no other block touches it)

                // Level 2: 16 mids -> final accumulator.
                const unsigned long long gcontrib = msum | COUNT_ONE;
                const unsigned long long gold = atomicAdd(&g_acc, gcontrib);
                if ((gold >> 56) == (unsigned long long)(NMID - 1)) {
                    const unsigned long long total = (gold + gcontrib) & SUM_MASK;
                    out[0] = (float)((double)total * FIX_INV);  // mean over B=1
                    g_acc = 0ULL;   // re-arm for next graph replay
                }
            }
        }
    }
}

extern "C" void kernel_launch(void* const* d_in, const int* in_sizes, int n_in,
                              void* d_out, int out_size)
{
    const float* projs = (const float*)d_in[0];
    float* out = (float*)d_out;

    // sigma = MU0 * tan((theta[127] - theta[29]) / 2), theta_k = 2*pi*k/128
    const double two_pi = 6.283185307179586;
    const double th_i = two_pi * 127.0 / 128.0;
    const double th_j = two_pi * 29.0 / 128.0;
    const float sigma = (float)((double)MU0 * tan((th_i - th_j) * 0.5));

    edcc_fused_kernel<<<NBLOCKS, 256>>>(projs, sigma, out);
}